// round 12
// baseline (speedup 1.0000x reference)
#include <cuda_runtime.h>
#include <cuda_fp16.h>
#include <cstdint>

#define D_MODEL 1024
#define N_EXP   8
#define N_TOK   8192
#define CAP     8192
#define MB_MAX  64
#define BM      128
#define BN      128
#define KTILES  32
#define NTHREADS 128
#define STAGE_B 8192          // A-only stage (8KB)
#define SMEM_T  (3 * STAGE_B) // 24 KB

// ---------------- device scratch ----------------
__device__ int    g_cnt[N_EXP];
__device__ int    g_tok[N_EXP * CAP];
__device__ float  g_wgt[N_EXP * CAP];
// fragment-permuted fp16 tiles: [e][mb][kt][4096 halves]
__device__ __half g_A1h[(size_t)N_EXP * MB_MAX * KTILES * 4096];
__device__ __half g_A2h[(size_t)N_EXP * MB_MAX * KTILES * 4096];
// fragment-permuted fp16 weights: [e][nb(8)][kt][4096 halves]
__device__ __half g_W1h[(size_t)N_EXP * 8 * KTILES * 4096];
__device__ __half g_W2h[(size_t)N_EXP * 8 * KTILES * 4096];

// ---------------- helpers ----------------
__device__ __forceinline__ uint32_t smem_u32(const void* p) {
    uint32_t a;
    asm("{ .reg .u64 t; cvta.to.shared.u64 t, %1; cvt.u32.u64 %0, t; }" : "=r"(a) : "l"(p));
    return a;
}
__device__ __forceinline__ void mma_f16(float* c, const uint32_t* a, const uint32_t* b) {
    asm volatile(
        "mma.sync.aligned.m16n8k16.row.col.f32.f16.f16.f32 "
        "{%0,%1,%2,%3}, {%4,%5,%6,%7}, {%8,%9}, {%0,%1,%2,%3};"
        : "+f"(c[0]), "+f"(c[1]), "+f"(c[2]), "+f"(c[3])
        : "r"(a[0]), "r"(a[1]), "r"(a[2]), "r"(a[3]),
          "r"(b[0]), "r"(b[1]));
}
#define CP_ASYNC16(dst, src) \
    asm volatile("cp.async.cg.shared.global [%0], [%1], 16;" :: "r"(dst), "l"(src))
#define CP_COMMIT()  asm volatile("cp.async.commit_group;" ::: "memory")
#define CP_WAIT1()   asm volatile("cp.async.wait_group 1;" ::: "memory")
#define LDS128(r, a) \
    asm volatile("ld.shared.v4.b32 {%0,%1,%2,%3}, [%4];" \
        : "=r"((r)[0]), "=r"((r)[1]), "=r"((r)[2]), "=r"((r)[3]) : "r"(a))

// fp16 m16n8k16 fragment slots (indices in halves), r in 0..127, k in 0..31
__device__ __forceinline__ int a_fidx16(int r, int k) {
    return (((r >> 4) * 2 + (k >> 4)) << 8) +
           (((r & 7) * 4 + ((k >> 1) & 3)) << 3) +
           ((((r >> 3) & 1) + 2 * ((k >> 3) & 1)) << 1) + (k & 1);
}
__device__ __forceinline__ int b_fidx16(int n, int k) {
    return (((n >> 3) * 2 + (k >> 4)) << 7) +
           (((n & 7) * 4 + ((k >> 1) & 3)) << 2) +
           (((k >> 3) & 1) << 1) + (k & 1);
}

// ---------------- kernel: reset counters ----------------
__global__ void zero_cnt_kernel() {
    if (threadIdx.x < N_EXP) g_cnt[threadIdx.x] = 0;
}

// ---------------- kernel: gating + top-2 ----------------
__global__ void gate_kernel(const float* __restrict__ x,
                            const float* __restrict__ Wg,
                            const float* __restrict__ bg) {
    int tok  = blockIdx.x * 8 + (threadIdx.x >> 5);
    int lane = threadIdx.x & 31;
    if (tok >= N_TOK) return;
    const float* xr = x + (size_t)tok * D_MODEL;

    float s[8];
#pragma unroll
    for (int e = 0; e < 8; e++) s[e] = 0.f;
    for (int k = lane; k < D_MODEL; k += 32) {
        float xv = xr[k];
        const float4* wr = (const float4*)(Wg + (size_t)k * N_EXP);
        float4 w0 = wr[0], w1 = wr[1];
        s[0] += xv * w0.x; s[1] += xv * w0.y; s[2] += xv * w0.z; s[3] += xv * w0.w;
        s[4] += xv * w1.x; s[5] += xv * w1.y; s[6] += xv * w1.z; s[7] += xv * w1.w;
    }
#pragma unroll
    for (int e = 0; e < 8; e++)
#pragma unroll
        for (int off = 16; off > 0; off >>= 1)
            s[e] += __shfl_xor_sync(0xffffffffu, s[e], off);

    if (lane == 0) {
        float best = -3.4e38f, best2 = -3.4e38f;
        int e0 = 0, e1 = 0;
#pragma unroll
        for (int e = 0; e < 8; e++) {
            float v = s[e] + bg[e];
            if (v > best)       { best2 = best; e1 = e0; best = v; e0 = e; }
            else if (v > best2) { best2 = v; e1 = e; }
        }
        int p0 = atomicAdd(&g_cnt[e0], 1);
        g_tok[e0 * CAP + p0] = tok;
        g_wgt[e0 * CAP + p0] = best;
        int p1 = atomicAdd(&g_cnt[e1], 1);
        g_tok[e1 * CAP + p1] = tok;
        g_wgt[e1 * CAP + p1] = best2;
    }
}

// ---------------- kernel: weight permute + fp16 convert ----------------
__global__ void w_perm_kernel(const float* __restrict__ W, int which) {
    __shared__ __half stg[4096];
    __half* dst = which ? g_W2h : g_W1h;
    const int kt = blockIdx.x, nb = blockIdx.y, e = blockIdx.z;
    const int tid = threadIdx.x;
    const int kr  = tid >> 3;
    const int nc8 = tid & 7;
    const float* Ws = W + (size_t)e * D_MODEL * D_MODEL;
#pragma unroll
    for (int i = 0; i < 4; i++) {
        int n_in = nc8 * 16 + i * 4;
        float4 v = *(const float4*)(Ws + (size_t)(kt * 32 + kr) * D_MODEL + nb * 128 + n_in);
        stg[b_fidx16(n_in + 0, kr)] = __float2half_rn(v.x);
        stg[b_fidx16(n_in + 1, kr)] = __float2half_rn(v.y);
        stg[b_fidx16(n_in + 2, kr)] = __float2half_rn(v.z);
        stg[b_fidx16(n_in + 3, kr)] = __float2half_rn(v.w);
    }
    __syncthreads();
    uint4* d4 = (uint4*)(dst + ((size_t)(e * 8 + nb) * KTILES + kt) * 4096);
    const uint4* s4 = (const uint4*)stg;
    d4[tid]       = s4[tid];
    d4[tid + 256] = s4[tid + 256];
}

// ---------------- kernel: gather + fp16 convert + permute X -> g_A1h ------
__global__ void a1_perm_kernel(const float* __restrict__ x) {
    __shared__ __half stg[4096];
    const int mb = blockIdx.x, e = blockIdx.y;
    const int cnt = g_cnt[e];
    if (mb * BM >= cnt) return;
    const int tid  = threadIdx.x;
    const int r    = tid >> 1;
    const int hlf  = tid & 1;
    int ai  = mb * BM + r;
    int tok = (ai < cnt) ? g_tok[e * CAP + ai] : g_tok[e * CAP];
    const float* src = x + (size_t)tok * D_MODEL;
    __half* dstb = g_A1h + (size_t)(e * MB_MAX + mb) * KTILES * 4096;

    for (int kt = 0; kt < KTILES; kt++) {
#pragma unroll
        for (int i = 0; i < 4; i++) {
            int k_in = hlf * 16 + i * 4;
            float4 v = *(const float4*)(src + kt * 32 + k_in);
            stg[a_fidx16(r, k_in + 0)] = __float2half_rn(v.x);
            stg[a_fidx16(r, k_in + 1)] = __float2half_rn(v.y);
            stg[a_fidx16(r, k_in + 2)] = __float2half_rn(v.z);
            stg[a_fidx16(r, k_in + 3)] = __float2half_rn(v.w);
        }
        __syncthreads();
        uint4* d4 = (uint4*)(dstb + (size_t)kt * 4096);
        const uint4* s4 = (const uint4*)stg;
        d4[tid]       = s4[tid];
        d4[tid + 256] = s4[tid + 256];
        __syncthreads();
    }
}

// ---------------- kernel: grouped GEMM (fp16, B global->register) ----------
// BM=128, BN=128, 128 threads, 4 warps (2m x 2n), warp tile 64x64.
// A: 3-stage cp.async ring (8KB/stage). B: LDG.64 direct to registers,
// prefetched one full k-tile (~565 cyc) ahead, double-buffered.
template <bool FIRST>
__global__ void __launch_bounds__(NTHREADS, 2)
moe_gemm(const float* __restrict__ bias, float* __restrict__ out) {
    const int e   = blockIdx.z;
    const int cnt = g_cnt[e];
    const int mb  = blockIdx.y;
    if (mb * BM >= cnt) return;
    const int nb  = blockIdx.x;

    extern __shared__ __align__(128) char smem[];
    const uint32_t sb = smem_u32(smem);
    const int tid  = threadIdx.x;
    const int lane = tid & 31;
    const int warp = tid >> 5;
    const int wm   = warp >> 1;          // 0..1 (64-row)
    const int wn   = warp & 1;           // 0..1 (64-col)
    const int g    = lane >> 2;
    const int tg   = lane & 3;

    const __half* Asrc = (FIRST ? g_A1h : g_A2h) + (size_t)(e * MB_MAX + mb) * KTILES * 4096;
    const __half* Bsrc = (FIRST ? g_W1h : g_W2h) + (size_t)(e * 8 + nb) * KTILES * 4096;
    // per-thread B fragment base (halves): warp covers wn*2048, lane*4 within 256B bursts
    const __half* Bw = Bsrc + wn * 2048 + lane * 4;

    float c[32][4];
#pragma unroll
    for (int i = 0; i < 32; i++)
#pragma unroll
        for (int j = 0; j < 4; j++) c[i][j] = 0.f;

    auto load_stage = [&](int kt, int s) {
        uint32_t da = sb + s * STAGE_B + tid * 16;
        const char* sa = (const char*)(Asrc + (size_t)kt * 4096) + tid * 16;
#pragma unroll
        for (int cc = 0; cc < 4; cc++)
            CP_ASYNC16(da + cc * 2048, sa + cc * 2048);
    };
    // load all B fragments of k-tile kt into breg[kk][ni][2]
    auto load_b_tile = [&](int kt, uint32_t breg[2][8][2]) {
        const __half* p = Bw + (size_t)kt * 4096;
#pragma unroll
        for (int kk = 0; kk < 2; kk++)
#pragma unroll
            for (int ni = 0; ni < 8; ni++) {
                uint2 v = __ldg((const uint2*)(p + kk * 128 + ni * 256));
                breg[kk][ni][0] = v.x;
                breg[kk][ni][1] = v.y;
            }
    };

    load_stage(0, 0); CP_COMMIT();
    load_stage(1, 1); CP_COMMIT();

    uint32_t b0[2][8][2], b1[2][8][2];
    load_b_tile(0, b0);

    const uint32_t aoff = wm * 4096 + lane * 16;

    auto ktile_iter = [&](int it, uint32_t bcur[2][8][2], uint32_t bnxt[2][8][2]) {
        CP_WAIT1();
        __syncthreads();
        if (it + 2 < KTILES) load_stage(it + 2, (it + 2) % 3);
        CP_COMMIT();
        if (it + 1 < KTILES) load_b_tile(it + 1, bnxt);

        const uint32_t st = sb + (it % 3) * STAGE_B;
#pragma unroll
        for (int kk = 0; kk < 2; kk++) {
            uint32_t a[4][4];
#pragma unroll
            for (int mi = 0; mi < 4; mi++)
                LDS128(a[mi], st + aoff + mi * 1024 + kk * 512);
#pragma unroll
            for (int mi = 0; mi < 4; mi++)
#pragma unroll
                for (int ni = 0; ni < 8; ni++)
                    mma_f16(c[mi * 8 + ni], a[mi], bcur[kk][ni]);
        }
    };

    for (int it = 0; it < KTILES; it += 2) {
        ktile_iter(it,     b0, b1);
        ktile_iter(it + 1, b1, b0);
    }

    // ---- epilogue ----
    const float* brow = bias + e * D_MODEL;
#pragma unroll
    for (int mi = 0; mi < 4; mi++) {
#pragma unroll
        for (int ni = 0; ni < 8; ni++) {
#pragma unroll
            for (int j = 0; j < 4; j++) {
                int r_blk = wm * 64 + mi * 16 + g + 8 * (j >> 1);
                int grow  = mb * BM + r_blk;
                if (grow >= cnt) continue;
                int n_glob = nb * BN + wn * 64 + ni * 8 + 2 * tg + (j & 1);
                float v = c[mi * 8 + ni][j] + __ldg(brow + n_glob);
                if (FIRST) {
                    v = fmaxf(v, 0.f);
                    int kt = n_glob >> 5, k_in = n_glob & 31;
                    g_A2h[((size_t)(e * MB_MAX + mb) * KTILES + kt) * 4096 +
                          a_fidx16(r_blk, k_in)] = __float2half_rn(v);
                } else {
                    float w = g_wgt[e * CAP + grow];
                    atomicAdd(out + (size_t)g_tok[e * CAP + grow] * D_MODEL + n_glob,
                              v * w);
                }
            }
        }
    }
}

// ---------------- launch ----------------
extern "C" void kernel_launch(void* const* d_in, const int* in_sizes, int n_in,
                              void* d_out, int out_size) {
    const float* x  = (const float*)d_in[0];
    const float* Wg = (const float*)d_in[1];
    const float* bg = (const float*)d_in[2];
    const float* W1 = (const float*)d_in[3];
    const float* b1 = (const float*)d_in[4];
    const float* W2 = (const float*)d_in[5];
    const float* b2 = (const float*)d_in[6];
    float* out = (float*)d_out;

    cudaFuncSetAttribute(moe_gemm<true>,
                         cudaFuncAttributeMaxDynamicSharedMemorySize, SMEM_T);
    cudaFuncSetAttribute(moe_gemm<false>,
                         cudaFuncAttributeMaxDynamicSharedMemorySize, SMEM_T);

    cudaMemsetAsync(out, 0, (size_t)out_size * sizeof(float));
    zero_cnt_kernel<<<1, 32>>>();
    gate_kernel<<<N_TOK / 8, 256>>>(x, Wg, bg);

    dim3 wg(KTILES, 8, N_EXP);
    w_perm_kernel<<<wg, 256>>>(W1, 0);
    w_perm_kernel<<<wg, 256>>>(W2, 1);
    a1_perm_kernel<<<dim3(MB_MAX, N_EXP), 256>>>(x);

    dim3 grid(D_MODEL / BN, MB_MAX, N_EXP);   // (8, 64, 8)
    moe_gemm<true><<<grid, NTHREADS, SMEM_T>>>(b1, nullptr);
    moe_gemm<false><<<grid, NTHREADS, SMEM_T>>>(b2, out);
}

// round 13
// speedup vs baseline: 1.1395x; 1.1395x over previous
#include <cuda_runtime.h>
#include <cuda_fp16.h>
#include <cstdint>

#define D_MODEL 1024
#define N_EXP   8
#define N_TOK   8192
#define CAP     8192
#define MB_MAX  64
#define BM      128
#define BN      128
#define KTILES  32
#define NTHREADS 128
#define STAGE_B 16384         // 8KB A + 8KB B per stage
#define SMEM_T  (3 * STAGE_B) // 48 KB
#define N_A1    512
#define N_G1    4096
#define T_G1    N_A1                // first gemm1 tile id
#define T_G2    (N_A1 + N_G1)       // first gemm2 tile id
#define T_TOT   (N_A1 + 2 * N_G1)   // 8704
#define NPERSIST 304

// ---------------- device scratch ----------------
__device__ int    g_cnt[N_EXP];
__device__ int    g_tok[N_EXP * CAP];
__device__ float  g_wgt[N_EXP * CAP];
__device__ int    g_a1done[N_A1];
__device__ int    g_g1done[N_A1];
__device__ int    g_tile_ctr;
// fragment-permuted fp16 tiles: [e][mb][kt][4096 halves]
__device__ __half g_A1h[(size_t)N_EXP * MB_MAX * KTILES * 4096];
__device__ __half g_A2h[(size_t)N_EXP * MB_MAX * KTILES * 4096];
// fragment-permuted fp16 weights: [e][nb(8)][kt][4096 halves]
__device__ __half g_W1h[(size_t)N_EXP * 8 * KTILES * 4096];
__device__ __half g_W2h[(size_t)N_EXP * 8 * KTILES * 4096];

// ---------------- helpers ----------------
__device__ __forceinline__ uint32_t smem_u32(const void* p) {
    uint32_t a;
    asm("{ .reg .u64 t; cvta.to.shared.u64 t, %1; cvt.u32.u64 %0, t; }" : "=r"(a) : "l"(p));
    return a;
}
__device__ __forceinline__ void mma_f16(float* c, const uint32_t* a, const uint32_t* b) {
    asm volatile(
        "mma.sync.aligned.m16n8k16.row.col.f32.f16.f16.f32 "
        "{%0,%1,%2,%3}, {%4,%5,%6,%7}, {%8,%9}, {%0,%1,%2,%3};"
        : "+f"(c[0]), "+f"(c[1]), "+f"(c[2]), "+f"(c[3])
        : "r"(a[0]), "r"(a[1]), "r"(a[2]), "r"(a[3]),
          "r"(b[0]), "r"(b[1]));
}
#define CP_ASYNC16(dst, src) \
    asm volatile("cp.async.cg.shared.global [%0], [%1], 16;" :: "r"(dst), "l"(src))
#define CP_COMMIT()  asm volatile("cp.async.commit_group;" ::: "memory")
#define CP_WAIT1()   asm volatile("cp.async.wait_group 1;" ::: "memory")
#define CP_WAIT0()   asm volatile("cp.async.wait_group 0;" ::: "memory")
#define LDS128(r, a) \
    asm volatile("ld.shared.v4.b32 {%0,%1,%2,%3}, [%4];" \
        : "=r"((r)[0]), "=r"((r)[1]), "=r"((r)[2]), "=r"((r)[3]) : "r"(a))
#define LDS64(r, a) \
    asm volatile("ld.shared.v2.b32 {%0,%1}, [%2];" \
        : "=r"((r)[0]), "=r"((r)[1]) : "r"(a))

// fp16 m16n8k16 fragment slots (indices in halves), r in 0..127, k in 0..31
__device__ __forceinline__ int a_fidx16(int r, int k) {
    return (((r >> 4) * 2 + (k >> 4)) << 8) +
           (((r & 7) * 4 + ((k >> 1) & 3)) << 3) +
           ((((r >> 3) & 1) + 2 * ((k >> 3) & 1)) << 1) + (k & 1);
}
__device__ __forceinline__ int b_fidx16(int n, int k) {
    return (((n >> 3) * 2 + (k >> 4)) << 7) +
           (((n & 7) * 4 + ((k >> 1) & 3)) << 2) +
           (((k >> 3) & 1) << 1) + (k & 1);
}

// ---------------- kernel: reset counters/flags ----------------
__global__ void zero_cnt_kernel() {
    int t = threadIdx.x;
    if (t < N_EXP) g_cnt[t] = 0;
    if (t == 0) g_tile_ctr = 0;
    for (int i = t; i < N_A1; i += 256) { g_a1done[i] = 0; g_g1done[i] = 0; }
}

// ---------------- kernel: gating + top-2 ----------------
__global__ void gate_kernel(const float* __restrict__ x,
                            const float* __restrict__ Wg,
                            const float* __restrict__ bg) {
    int tok  = blockIdx.x * 8 + (threadIdx.x >> 5);
    int lane = threadIdx.x & 31;
    if (tok >= N_TOK) return;
    const float* xr = x + (size_t)tok * D_MODEL;

    float s[8];
#pragma unroll
    for (int e = 0; e < 8; e++) s[e] = 0.f;
    for (int k = lane; k < D_MODEL; k += 32) {
        float xv = xr[k];
        const float4* wr = (const float4*)(Wg + (size_t)k * N_EXP);
        float4 w0 = wr[0], w1 = wr[1];
        s[0] += xv * w0.x; s[1] += xv * w0.y; s[2] += xv * w0.z; s[3] += xv * w0.w;
        s[4] += xv * w1.x; s[5] += xv * w1.y; s[6] += xv * w1.z; s[7] += xv * w1.w;
    }
#pragma unroll
    for (int e = 0; e < 8; e++)
#pragma unroll
        for (int off = 16; off > 0; off >>= 1)
            s[e] += __shfl_xor_sync(0xffffffffu, s[e], off);

    if (lane == 0) {
        float best = -3.4e38f, best2 = -3.4e38f;
        int e0 = 0, e1 = 0;
#pragma unroll
        for (int e = 0; e < 8; e++) {
            float v = s[e] + bg[e];
            if (v > best)       { best2 = best; e1 = e0; best = v; e0 = e; }
            else if (v > best2) { best2 = v; e1 = e; }
        }
        int p0 = atomicAdd(&g_cnt[e0], 1);
        g_tok[e0 * CAP + p0] = tok;
        g_wgt[e0 * CAP + p0] = best;
        int p1 = atomicAdd(&g_cnt[e1], 1);
        g_tok[e1 * CAP + p1] = tok;
        g_wgt[e1 * CAP + p1] = best2;
    }
}

// ---------------- kernel: weight permute + fp16 convert ----------------
__global__ void w_perm_kernel(const float* __restrict__ W, int which) {
    __shared__ __half stg[4096];
    __half* dst = which ? g_W2h : g_W1h;
    const int kt = blockIdx.x, nb = blockIdx.y, e = blockIdx.z;
    const int tid = threadIdx.x;
    const int kr  = tid >> 3;
    const int nc8 = tid & 7;
    const float* Ws = W + (size_t)e * D_MODEL * D_MODEL;
#pragma unroll
    for (int i = 0; i < 4; i++) {
        int n_in = nc8 * 16 + i * 4;
        float4 v = *(const float4*)(Ws + (size_t)(kt * 32 + kr) * D_MODEL + nb * 128 + n_in);
        stg[b_fidx16(n_in + 0, kr)] = __float2half_rn(v.x);
        stg[b_fidx16(n_in + 1, kr)] = __float2half_rn(v.y);
        stg[b_fidx16(n_in + 2, kr)] = __float2half_rn(v.z);
        stg[b_fidx16(n_in + 3, kr)] = __float2half_rn(v.w);
    }
    __syncthreads();
    uint4* d4 = (uint4*)(dst + ((size_t)(e * 8 + nb) * KTILES + kt) * 4096);
    const uint4* s4 = (const uint4*)stg;
    d4[tid]       = s4[tid];
    d4[tid + 256] = s4[tid + 256];
}

// ---------------- GEMM tile (device fn, R10 mainloop) ----------------
template <bool FIRST>
__device__ __forceinline__ void gemm_tile(int e, int mb, int nb, int cnt,
                                          char* smem, uint32_t sb, int tid,
                                          const float* __restrict__ bias,
                                          float* __restrict__ out) {
    const int lane = tid & 31;
    const int warp = tid >> 5;
    const int wm   = warp >> 1;
    const int wn   = warp & 1;
    const int g    = lane >> 2;
    const int tg   = lane & 3;

    const __half* Asrc = (FIRST ? g_A1h : g_A2h) + (size_t)(e * MB_MAX + mb) * KTILES * 4096;
    const __half* Bsrc = (FIRST ? g_W1h : g_W2h) + (size_t)(e * 8 + nb) * KTILES * 4096;

    float c[32][4];
#pragma unroll
    for (int i = 0; i < 32; i++)
#pragma unroll
        for (int j = 0; j < 4; j++) c[i][j] = 0.f;

    auto load_stage = [&](int kt, int s) {
        uint32_t da = sb + s * STAGE_B + tid * 16;
        const char* sa = (const char*)(Asrc + (size_t)kt * 4096) + tid * 16;
        const char* sw = (const char*)(Bsrc + (size_t)kt * 4096) + tid * 16;
#pragma unroll
        for (int cc = 0; cc < 4; cc++) {
            CP_ASYNC16(da + cc * 2048,        sa + cc * 2048);
            CP_ASYNC16(da + 8192 + cc * 2048, sw + cc * 2048);
        }
    };

    CP_WAIT0();                      // drain any leftovers from previous tile
    load_stage(0, 0); CP_COMMIT();
    load_stage(1, 1); CP_COMMIT();

    const uint32_t aoff = wm * 4096 + lane * 16;
    const uint32_t boff = 8192 + wn * 4096 + lane * 8;

    for (int it = 0; it < KTILES; it++) {
        CP_WAIT1();
        __syncthreads();
        if (it + 2 < KTILES) load_stage(it + 2, (it + 2) % 3);
        CP_COMMIT();

        const uint32_t st = sb + (it % 3) * STAGE_B;
#pragma unroll
        for (int kk = 0; kk < 2; kk++) {
            uint32_t a[4][4], b[8][2];
#pragma unroll
            for (int mi = 0; mi < 4; mi++)
                LDS128(a[mi], st + aoff + mi * 1024 + kk * 512);
#pragma unroll
            for (int ni = 0; ni < 8; ni++)
                LDS64(b[ni], st + boff + ni * 512 + kk * 256);
#pragma unroll
            for (int mi = 0; mi < 4; mi++)
#pragma unroll
                for (int ni = 0; ni < 8; ni++)
                    mma_f16(c[mi * 8 + ni], a[mi], b[ni]);
        }
    }

    const float* brow = bias + e * D_MODEL;
    if (FIRST) {
        // staged epilogue: permuted layout in smem, then contiguous 32KB copy-out
        __syncthreads();
        __half2* ep2 = (__half2*)smem;
#pragma unroll
        for (int mi = 0; mi < 4; mi++) {
#pragma unroll
            for (int ni = 0; ni < 8; ni++) {
#pragma unroll
                for (int jp = 0; jp < 2; jp++) {
                    int r_blk = wm * 64 + mi * 16 + g + 8 * jp;
                    int n0    = wn * 64 + ni * 8 + 2 * tg;     // even, 0..126
                    int n_glob = nb * BN + n0;
                    float v0 = fmaxf(c[mi * 8 + ni][jp * 2 + 0] + __ldg(brow + n_glob), 0.f);
                    float v1 = fmaxf(c[mi * 8 + ni][jp * 2 + 1] + __ldg(brow + n_glob + 1), 0.f);
                    int idx = (n0 >> 5) * 4096 + a_fidx16(r_blk, n0 & 31); // even
                    ep2[idx >> 1] = __floats2half2_rn(v0, v1);
                }
            }
        }
        __syncthreads();
        uint4* d4 = (uint4*)(g_A2h + ((size_t)(e * MB_MAX + mb) * KTILES + nb * 4) * 4096);
        const uint4* s4 = (const uint4*)smem;
#pragma unroll
        for (int i = 0; i < 16; i++)
            d4[tid + i * 128] = s4[tid + i * 128];
        __threadfence();
        __syncthreads();
        if (tid == 0) atomicAdd(&g_g1done[e * MB_MAX + mb], 1);
    } else {
#pragma unroll
        for (int mi = 0; mi < 4; mi++) {
#pragma unroll
            for (int ni = 0; ni < 8; ni++) {
#pragma unroll
                for (int j = 0; j < 4; j++) {
                    int r_blk = wm * 64 + mi * 16 + g + 8 * (j >> 1);
                    int grow  = mb * BM + r_blk;
                    if (grow >= cnt) continue;
                    int n_glob = nb * BN + wn * 64 + ni * 8 + 2 * tg + (j & 1);
                    float v = c[mi * 8 + ni][j] + __ldg(brow + n_glob);
                    float w = g_wgt[e * CAP + grow];
                    atomicAdd(out + (size_t)g_tok[e * CAP + grow] * D_MODEL + n_glob,
                              v * w);
                }
            }
        }
    }
}

// ---------------- persistent fused kernel ----------------
__global__ void __launch_bounds__(NTHREADS, 2)
moe_persist(const float* __restrict__ x,
            const float* __restrict__ b1,
            const float* __restrict__ b2,
            float* __restrict__ out) {
    extern __shared__ __align__(128) char smem[];
    const uint32_t sb = smem_u32(smem);
    const int tid = threadIdx.x;
    __shared__ int s_tile;

    for (;;) {
        __syncthreads();
        if (tid == 0) s_tile = atomicAdd(&g_tile_ctr, 1);
        __syncthreads();
        const int t = s_tile;
        if (t >= T_TOT) break;

        if (t < T_G1) {
            // ---- phase 0: gather + fp16 convert + permute one (e,mb) A1 tile ----
            const int e = t >> 6, mb = t & 63;
            const int cnt = g_cnt[e];
            if (mb * BM < cnt) {
                const int r = tid;
                int ai  = mb * BM + r;
                int tok = (ai < cnt) ? g_tok[e * CAP + ai] : g_tok[e * CAP];
                const float* src = x + (size_t)tok * D_MODEL;
                __half* dstb = g_A1h + (size_t)(e * MB_MAX + mb) * KTILES * 4096;
                __half* stg = (__half*)smem;
                for (int kt = 0; kt < KTILES; kt++) {
#pragma unroll
                    for (int i = 0; i < 8; i++) {
                        float4 v = *(const float4*)(src + kt * 32 + i * 4);
                        stg[a_fidx16(r, i * 4 + 0)] = __float2half_rn(v.x);
                        stg[a_fidx16(r, i * 4 + 1)] = __float2half_rn(v.y);
                        stg[a_fidx16(r, i * 4 + 2)] = __float2half_rn(v.z);
                        stg[a_fidx16(r, i * 4 + 3)] = __float2half_rn(v.w);
                    }
                    __syncthreads();
                    uint4* d4 = (uint4*)(dstb + (size_t)kt * 4096);
                    const uint4* s4 = (const uint4*)stg;
#pragma unroll
                    for (int i = 0; i < 4; i++)
                        d4[tid + i * 128] = s4[tid + i * 128];
                    __syncthreads();
                }
                __threadfence();
            }
            if (tid == 0) atomicExch(&g_a1done[t], 1);
        } else if (t < T_G2) {
            // ---- phase 1: GEMM1 tile ----
            const int t2 = t - T_G1;
            const int em = t2 >> 3;          // e*64+mb
            const int nb = t2 & 7;
            const int e  = em >> 6, mb = em & 63;
            const int cnt = g_cnt[e];
            if (mb * BM >= cnt) continue;
            if (tid == 0) {
                volatile int* f = &g_a1done[em];
                while (*f == 0) __nanosleep(64);
            }
            __syncthreads();
            gemm_tile<true>(e, mb, nb, cnt, smem, sb, tid, b1, out);
        } else {
            // ---- phase 2: GEMM2 tile ----
            const int t2 = t - T_G2;
            const int em = t2 >> 3;
            const int nb = t2 & 7;
            const int e  = em >> 6, mb = em & 63;
            const int cnt = g_cnt[e];
            if (mb * BM >= cnt) continue;
            if (tid == 0) {
                volatile int* f = &g_g1done[em];
                while (*f < 8) __nanosleep(64);
            }
            __syncthreads();
            gemm_tile<false>(e, mb, nb, cnt, smem, sb, tid, b2, out);
        }
    }
}

// ---------------- launch ----------------
extern "C" void kernel_launch(void* const* d_in, const int* in_sizes, int n_in,
                              void* d_out, int out_size) {
    const float* x  = (const float*)d_in[0];
    const float* Wg = (const float*)d_in[1];
    const float* bg = (const float*)d_in[2];
    const float* W1 = (const float*)d_in[3];
    const float* b1 = (const float*)d_in[4];
    const float* W2 = (const float*)d_in[5];
    const float* b2 = (const float*)d_in[6];
    float* out = (float*)d_out;

    cudaFuncSetAttribute(moe_persist,
                         cudaFuncAttributeMaxDynamicSharedMemorySize, SMEM_T);

    cudaMemsetAsync(out, 0, (size_t)out_size * sizeof(float));
    zero_cnt_kernel<<<1, 256>>>();
    gate_kernel<<<N_TOK / 8, 256>>>(x, Wg, bg);

    dim3 wg(KTILES, 8, N_EXP);
    w_perm_kernel<<<wg, 256>>>(W1, 0);
    w_perm_kernel<<<wg, 256>>>(W2, 1);

    moe_persist<<<NPERSIST, NTHREADS, SMEM_T>>>(x, b1, b2, out);
}

// round 14
// speedup vs baseline: 1.1871x; 1.0418x over previous
#include <cuda_runtime.h>
#include <cuda_fp16.h>
#include <cstdint>

#define D_MODEL 1024
#define N_EXP   8
#define N_TOK   8192
#define CAP     8192
#define MB_MAX  64
#define BM      128
#define BN      128
#define KTILES  32
#define NTHREADS 128
#define STAGE_B 16384         // 8KB A + 8KB B per stage
#define NSTAGE  4
#define SMEM_T  (NSTAGE * STAGE_B) // 64 KB

// ---------------- device scratch ----------------
__device__ int    g_cnt[N_EXP];
__device__ int    g_tok[N_EXP * CAP];
__device__ float  g_wgt[N_EXP * CAP];
// fragment-permuted fp16 tiles: [e][mb][kt][4096 halves]
__device__ __half g_A1h[(size_t)N_EXP * MB_MAX * KTILES * 4096];
__device__ __half g_A2h[(size_t)N_EXP * MB_MAX * KTILES * 4096];
// fragment-permuted fp16 weights: [e][nb(8)][kt][4096 halves]
__device__ __half g_W1h[(size_t)N_EXP * 8 * KTILES * 4096];
__device__ __half g_W2h[(size_t)N_EXP * 8 * KTILES * 4096];

// ---------------- helpers ----------------
__device__ __forceinline__ uint32_t smem_u32(const void* p) {
    uint32_t a;
    asm("{ .reg .u64 t; cvta.to.shared.u64 t, %1; cvt.u32.u64 %0, t; }" : "=r"(a) : "l"(p));
    return a;
}
__device__ __forceinline__ void mma_f16(float* c, const uint32_t* a, const uint32_t* b) {
    asm volatile(
        "mma.sync.aligned.m16n8k16.row.col.f32.f16.f16.f32 "
        "{%0,%1,%2,%3}, {%4,%5,%6,%7}, {%8,%9}, {%0,%1,%2,%3};"
        : "+f"(c[0]), "+f"(c[1]), "+f"(c[2]), "+f"(c[3])
        : "r"(a[0]), "r"(a[1]), "r"(a[2]), "r"(a[3]),
          "r"(b[0]), "r"(b[1]));
}
#define CP_ASYNC16(dst, src) \
    asm volatile("cp.async.cg.shared.global [%0], [%1], 16;" :: "r"(dst), "l"(src))
#define CP_COMMIT()  asm volatile("cp.async.commit_group;" ::: "memory")
#define CP_WAIT2()   asm volatile("cp.async.wait_group 2;" ::: "memory")
#define LDS128(r, a) \
    asm volatile("ld.shared.v4.b32 {%0,%1,%2,%3}, [%4];" \
        : "=r"((r)[0]), "=r"((r)[1]), "=r"((r)[2]), "=r"((r)[3]) : "r"(a))
#define LDS64(r, a) \
    asm volatile("ld.shared.v2.b32 {%0,%1}, [%2];" \
        : "=r"((r)[0]), "=r"((r)[1]) : "r"(a))

// fp16 m16n8k16 fragment slots (indices in halves), r in 0..127, k in 0..31
__device__ __forceinline__ int a_fidx16(int r, int k) {
    return (((r >> 4) * 2 + (k >> 4)) << 8) +
           (((r & 7) * 4 + ((k >> 1) & 3)) << 3) +
           ((((r >> 3) & 1) + 2 * ((k >> 3) & 1)) << 1) + (k & 1);
}
__device__ __forceinline__ int b_fidx16(int n, int k) {
    return (((n >> 3) * 2 + (k >> 4)) << 7) +
           (((n & 7) * 4 + ((k >> 1) & 3)) << 2) +
           (((k >> 3) & 1) << 1) + (k & 1);
}

// ---------------- kernel: reset counters ----------------
__global__ void zero_cnt_kernel() {
    if (threadIdx.x < N_EXP) g_cnt[threadIdx.x] = 0;
}

// ---------------- kernel: gating + top-2 ----------------
__global__ void gate_kernel(const float* __restrict__ x,
                            const float* __restrict__ Wg,
                            const float* __restrict__ bg) {
    int tok  = blockIdx.x * 8 + (threadIdx.x >> 5);
    int lane = threadIdx.x & 31;
    if (tok >= N_TOK) return;
    const float* xr = x + (size_t)tok * D_MODEL;

    float s[8];
#pragma unroll
    for (int e = 0; e < 8; e++) s[e] = 0.f;
    for (int k = lane; k < D_MODEL; k += 32) {
        float xv = xr[k];
        const float4* wr = (const float4*)(Wg + (size_t)k * N_EXP);
        float4 w0 = wr[0], w1 = wr[1];
        s[0] += xv * w0.x; s[1] += xv * w0.y; s[2] += xv * w0.z; s[3] += xv * w0.w;
        s[4] += xv * w1.x; s[5] += xv * w1.y; s[6] += xv * w1.z; s[7] += xv * w1.w;
    }
#pragma unroll
    for (int e = 0; e < 8; e++)
#pragma unroll
        for (int off = 16; off > 0; off >>= 1)
            s[e] += __shfl_xor_sync(0xffffffffu, s[e], off);

    if (lane == 0) {
        float best = -3.4e38f, best2 = -3.4e38f;
        int e0 = 0, e1 = 0;
#pragma unroll
        for (int e = 0; e < 8; e++) {
            float v = s[e] + bg[e];
            if (v > best)       { best2 = best; e1 = e0; best = v; e0 = e; }
            else if (v > best2) { best2 = v; e1 = e; }
        }
        int p0 = atomicAdd(&g_cnt[e0], 1);
        g_tok[e0 * CAP + p0] = tok;
        g_wgt[e0 * CAP + p0] = best;
        int p1 = atomicAdd(&g_cnt[e1], 1);
        g_tok[e1 * CAP + p1] = tok;
        g_wgt[e1 * CAP + p1] = best2;
    }
}

// ---------------- kernel: fused weight permute + fp16 convert ----------------
// blockIdx.z encodes (which, e); thread handles k-pairs -> half2 staging stores
__global__ void w_perm_kernel(const float* __restrict__ W1,
                              const float* __restrict__ W2) {
    __shared__ __half stg[4096];
    const int which = blockIdx.z >> 3;
    const int e     = blockIdx.z & 7;
    const float* W  = which ? W2 : W1;
    __half* dst     = which ? g_W2h : g_W1h;
    const int kt = blockIdx.x, nb = blockIdx.y;
    const int tid = threadIdx.x;
    const int kp  = tid >> 4;          // k-pair 0..15 (k = 2*kp, 2*kp+1)
    const int nc  = tid & 15;          // column group (8 n each)
    const float* Ws = W + (size_t)e * D_MODEL * D_MODEL;
    __half2* stg2 = (__half2*)stg;
#pragma unroll
    for (int i = 0; i < 2; i++) {
        int n_in = nc * 8 + i * 4;
        const float* r0 = Ws + (size_t)(kt * 32 + 2 * kp) * D_MODEL + nb * 128 + n_in;
        float4 v0 = *(const float4*)r0;
        float4 v1 = *(const float4*)(r0 + D_MODEL);
        // b_fidx16(n, 2kp) and b_fidx16(n, 2kp+1) are adjacent halves
        stg2[b_fidx16(n_in + 0, 2 * kp) >> 1] = __floats2half2_rn(v0.x, v1.x);
        stg2[b_fidx16(n_in + 1, 2 * kp) >> 1] = __floats2half2_rn(v0.y, v1.y);
        stg2[b_fidx16(n_in + 2, 2 * kp) >> 1] = __floats2half2_rn(v0.z, v1.z);
        stg2[b_fidx16(n_in + 3, 2 * kp) >> 1] = __floats2half2_rn(v0.w, v1.w);
    }
    __syncthreads();
    uint4* d4 = (uint4*)(dst + ((size_t)(e * 8 + nb) * KTILES + kt) * 4096);
    const uint4* s4 = (const uint4*)stg;
    d4[tid]       = s4[tid];
    d4[tid + 256] = s4[tid + 256];
}

// ---------------- kernel: gather + fp16 convert + permute X -> g_A1h ------
__global__ void a1_perm_kernel(const float* __restrict__ x) {
    __shared__ __half stg[4096];
    const int mb = blockIdx.x, e = blockIdx.y;
    const int cnt = g_cnt[e];
    if (mb * BM >= cnt) return;
    const int tid  = threadIdx.x;
    const int r    = tid >> 1;
    const int hlf  = tid & 1;
    int ai  = mb * BM + r;
    int tok = (ai < cnt) ? g_tok[e * CAP + ai] : g_tok[e * CAP];
    const float* src = x + (size_t)tok * D_MODEL;
    __half* dstb = g_A1h + (size_t)(e * MB_MAX + mb) * KTILES * 4096;

    for (int kt = 0; kt < KTILES; kt++) {
#pragma unroll
        for (int i = 0; i < 4; i++) {
            int k_in = hlf * 16 + i * 4;
            float4 v = *(const float4*)(src + kt * 32 + k_in);
            stg[a_fidx16(r, k_in + 0)] = __float2half_rn(v.x);
            stg[a_fidx16(r, k_in + 1)] = __float2half_rn(v.y);
            stg[a_fidx16(r, k_in + 2)] = __float2half_rn(v.z);
            stg[a_fidx16(r, k_in + 3)] = __float2half_rn(v.w);
        }
        __syncthreads();
        uint4* d4 = (uint4*)(dstb + (size_t)kt * 4096);
        const uint4* s4 = (const uint4*)stg;
        d4[tid]       = s4[tid];
        d4[tid + 256] = s4[tid + 256];
        __syncthreads();
    }
}

// ---------------- kernel: grouped GEMM (fp16, 4-stage deep pipeline) -------
// BM=128, BN=128, 128 threads, 4 warps (2m x 2n), warp tile 64x64.
// 4-stage cp.async ring (16KB/stage), wait_group 2 -> 2 k-tiles prefetch
// distance, one barrier per k-tile, 2 CTAs/SM.
template <bool FIRST>
__global__ void __launch_bounds__(NTHREADS, 2)
moe_gemm(const float* __restrict__ bias, float* __restrict__ out) {
    const int e   = blockIdx.z;
    const int cnt = g_cnt[e];
    const int mb  = blockIdx.y;
    if (mb * BM >= cnt) return;
    const int nb  = blockIdx.x;

    extern __shared__ __align__(128) char smem[];
    const uint32_t sb = smem_u32(smem);
    const int tid  = threadIdx.x;
    const int lane = tid & 31;
    const int warp = tid >> 5;
    const int wm   = warp >> 1;          // 0..1 (64-row)
    const int wn   = warp & 1;           // 0..1 (64-col)
    const int g    = lane >> 2;
    const int tg   = lane & 3;

    const __half* Asrc = (FIRST ? g_A1h : g_A2h) + (size_t)(e * MB_MAX + mb) * KTILES * 4096;
    const __half* Bsrc = (FIRST ? g_W1h : g_W2h) + (size_t)(e * 8 + nb) * KTILES * 4096;

    float c[32][4];
#pragma unroll
    for (int i = 0; i < 32; i++)
#pragma unroll
        for (int j = 0; j < 4; j++) c[i][j] = 0.f;

    // stage layout: [0,8K) A | [8K,16K) B
    auto load_stage = [&](int kt, int s) {
        uint32_t da = sb + s * STAGE_B + tid * 16;
        const char* sa = (const char*)(Asrc + (size_t)kt * 4096) + tid * 16;
        const char* sw = (const char*)(Bsrc + (size_t)kt * 4096) + tid * 16;
#pragma unroll
        for (int cc = 0; cc < 4; cc++) {
            CP_ASYNC16(da + cc * 2048,        sa + cc * 2048);
            CP_ASYNC16(da + 8192 + cc * 2048, sw + cc * 2048);
        }
    };

    load_stage(0, 0); CP_COMMIT();
    load_stage(1, 1); CP_COMMIT();
    load_stage(2, 2); CP_COMMIT();

    const uint32_t aoff = wm * 4096 + lane * 16;          // A frag base (bytes)
    const uint32_t boff = 8192 + wn * 4096 + lane * 8;    // B frag base (bytes)

    for (int it = 0; it < KTILES; it++) {
        CP_WAIT2();
        __syncthreads();
        // stage (it+3)&3 == (it-1)&3: its reads finished at prev barrier
        if (it + 3 < KTILES) load_stage(it + 3, (it + 3) & 3);
        CP_COMMIT();

        const uint32_t st = sb + (it & 3) * STAGE_B;
#pragma unroll
        for (int kk = 0; kk < 2; kk++) {
            uint32_t a[4][4], b[8][2];
#pragma unroll
            for (int mi = 0; mi < 4; mi++)
                LDS128(a[mi], st + aoff + mi * 1024 + kk * 512);
#pragma unroll
            for (int ni = 0; ni < 8; ni++)
                LDS64(b[ni], st + boff + ni * 512 + kk * 256);
#pragma unroll
            for (int mi = 0; mi < 4; mi++)
#pragma unroll
                for (int ni = 0; ni < 8; ni++)
                    mma_f16(c[mi * 8 + ni], a[mi], b[ni]);
        }
    }

    // ---- epilogue ----
    const float* brow = bias + e * D_MODEL;
#pragma unroll
    for (int mi = 0; mi < 4; mi++) {
#pragma unroll
        for (int ni = 0; ni < 8; ni++) {
#pragma unroll
            for (int j = 0; j < 4; j++) {
                int r_blk = wm * 64 + mi * 16 + g + 8 * (j >> 1);
                int grow  = mb * BM + r_blk;
                if (grow >= cnt) continue;
                int n_glob = nb * BN + wn * 64 + ni * 8 + 2 * tg + (j & 1);
                float v = c[mi * 8 + ni][j] + __ldg(brow + n_glob);
                if (FIRST) {
                    v = fmaxf(v, 0.f);
                    int kt = n_glob >> 5, k_in = n_glob & 31;
                    g_A2h[((size_t)(e * MB_MAX + mb) * KTILES + kt) * 4096 +
                          a_fidx16(r_blk, k_in)] = __float2half_rn(v);
                } else {
                    float w = g_wgt[e * CAP + grow];
                    atomicAdd(out + (size_t)g_tok[e * CAP + grow] * D_MODEL + n_glob,
                              v * w);
                }
            }
        }
    }
}

// ---------------- launch ----------------
extern "C" void kernel_launch(void* const* d_in, const int* in_sizes, int n_in,
                              void* d_out, int out_size) {
    const float* x  = (const float*)d_in[0];
    const float* Wg = (const float*)d_in[1];
    const float* bg = (const float*)d_in[2];
    const float* W1 = (const float*)d_in[3];
    const float* b1 = (const float*)d_in[4];
    const float* W2 = (const float*)d_in[5];
    const float* b2 = (const float*)d_in[6];
    float* out = (float*)d_out;

    cudaFuncSetAttribute(moe_gemm<true>,
                         cudaFuncAttributeMaxDynamicSharedMemorySize, SMEM_T);
    cudaFuncSetAttribute(moe_gemm<false>,
                         cudaFuncAttributeMaxDynamicSharedMemorySize, SMEM_T);

    cudaMemsetAsync(out, 0, (size_t)out_size * sizeof(float));
    zero_cnt_kernel<<<1, 32>>>();
    gate_kernel<<<N_TOK / 8, 256>>>(x, Wg, bg);

    dim3 wg(KTILES, 8, 16);                 // fused W1+W2 permute
    w_perm_kernel<<<wg, 256>>>(W1, W2);
    a1_perm_kernel<<<dim3(MB_MAX, N_EXP), 256>>>(x);

    dim3 grid(D_MODEL / BN, MB_MAX, N_EXP);   // (8, 64, 8)
    moe_gemm<true><<<grid, NTHREADS, SMEM_T>>>(b1, nullptr);
    moe_gemm<false><<<grid, NTHREADS, SMEM_T>>>(b2, out);
}

// round 15
// speedup vs baseline: 1.2623x; 1.0634x over previous
#include <cuda_runtime.h>
#include <cuda_fp16.h>
#include <cstdint>

#define D_MODEL 1024
#define N_EXP   8
#define N_TOK   8192
#define CAP     8192
#define MB_MAX  64
#define BM      128
#define BN      128
#define KTILES  32
#define NTHREADS 128
#define STAGE_B 16384         // 8KB A + 8KB B per stage
#define NSTAGE  4
#define SMEM_T  (NSTAGE * STAGE_B) // 64 KB

// ---------------- device scratch ----------------
__device__ int    g_cnt[N_EXP];
__device__ int    g_tok[N_EXP * CAP];
__device__ float  g_wgt[N_EXP * CAP];
// fragment-permuted fp16 tiles: [e][mb][kt][4096 halves]
__device__ __half g_A1h[(size_t)N_EXP * MB_MAX * KTILES * 4096];
__device__ __half g_A2h[(size_t)N_EXP * MB_MAX * KTILES * 4096];
// fragment-permuted fp16 weights: [e][nb(8)][kt][4096 halves]
__device__ __half g_W1h[(size_t)N_EXP * 8 * KTILES * 4096];
__device__ __half g_W2h[(size_t)N_EXP * 8 * KTILES * 4096];

// ---------------- helpers ----------------
__device__ __forceinline__ uint32_t smem_u32(const void* p) {
    uint32_t a;
    asm("{ .reg .u64 t; cvta.to.shared.u64 t, %1; cvt.u32.u64 %0, t; }" : "=r"(a) : "l"(p));
    return a;
}
__device__ __forceinline__ void mma_f16(float* c, const uint32_t* a, const uint32_t* b) {
    asm volatile(
        "mma.sync.aligned.m16n8k16.row.col.f32.f16.f16.f32 "
        "{%0,%1,%2,%3}, {%4,%5,%6,%7}, {%8,%9}, {%0,%1,%2,%3};"
        : "+f"(c[0]), "+f"(c[1]), "+f"(c[2]), "+f"(c[3])
        : "r"(a[0]), "r"(a[1]), "r"(a[2]), "r"(a[3]),
          "r"(b[0]), "r"(b[1]));
}
#define CP_ASYNC16(dst, src) \
    asm volatile("cp.async.cg.shared.global [%0], [%1], 16;" :: "r"(dst), "l"(src))
#define CP_COMMIT()  asm volatile("cp.async.commit_group;" ::: "memory")
#define CP_WAIT2()   asm volatile("cp.async.wait_group 2;" ::: "memory")
#define LDS128(r, a) \
    asm volatile("ld.shared.v4.b32 {%0,%1,%2,%3}, [%4];" \
        : "=r"((r)[0]), "=r"((r)[1]), "=r"((r)[2]), "=r"((r)[3]) : "r"(a))
#define LDS64(r, a) \
    asm volatile("ld.shared.v2.b32 {%0,%1}, [%2];" \
        : "=r"((r)[0]), "=r"((r)[1]) : "r"(a))

// fp16 m16n8k16 fragment slots (indices in halves), r in 0..127, k in 0..31
__device__ __forceinline__ int a_fidx16(int r, int k) {
    return (((r >> 4) * 2 + (k >> 4)) << 8) +
           (((r & 7) * 4 + ((k >> 1) & 3)) << 3) +
           ((((r >> 3) & 1) + 2 * ((k >> 3) & 1)) << 1) + (k & 1);
}
__device__ __forceinline__ int b_fidx16(int n, int k) {
    return (((n >> 3) * 2 + (k >> 4)) << 7) +
           (((n & 7) * 4 + ((k >> 1) & 3)) << 2) +
           (((k >> 3) & 1) << 1) + (k & 1);
}

// ---------------- kernel: reset counters ----------------
__global__ void zero_cnt_kernel() {
    if (threadIdx.x < N_EXP) g_cnt[threadIdx.x] = 0;
}

// ---------------- kernel: gating + top-2 ----------------
__global__ void gate_kernel(const float* __restrict__ x,
                            const float* __restrict__ Wg,
                            const float* __restrict__ bg) {
    int tok  = blockIdx.x * 8 + (threadIdx.x >> 5);
    int lane = threadIdx.x & 31;
    if (tok >= N_TOK) return;
    const float* xr = x + (size_t)tok * D_MODEL;

    float s[8];
#pragma unroll
    for (int e = 0; e < 8; e++) s[e] = 0.f;
    for (int k = lane; k < D_MODEL; k += 32) {
        float xv = xr[k];
        const float4* wr = (const float4*)(Wg + (size_t)k * N_EXP);
        float4 w0 = wr[0], w1 = wr[1];
        s[0] += xv * w0.x; s[1] += xv * w0.y; s[2] += xv * w0.z; s[3] += xv * w0.w;
        s[4] += xv * w1.x; s[5] += xv * w1.y; s[6] += xv * w1.z; s[7] += xv * w1.w;
    }
#pragma unroll
    for (int e = 0; e < 8; e++)
#pragma unroll
        for (int off = 16; off > 0; off >>= 1)
            s[e] += __shfl_xor_sync(0xffffffffu, s[e], off);

    if (lane == 0) {
        float best = -3.4e38f, best2 = -3.4e38f;
        int e0 = 0, e1 = 0;
#pragma unroll
        for (int e = 0; e < 8; e++) {
            float v = s[e] + bg[e];
            if (v > best)       { best2 = best; e1 = e0; best = v; e0 = e; }
            else if (v > best2) { best2 = v; e1 = e; }
        }
        int p0 = atomicAdd(&g_cnt[e0], 1);
        g_tok[e0 * CAP + p0] = tok;
        g_wgt[e0 * CAP + p0] = best;
        int p1 = atomicAdd(&g_cnt[e1], 1);
        g_tok[e1 * CAP + p1] = tok;
        g_wgt[e1 * CAP + p1] = best2;
    }
}

// ---------------- kernel: fused weight permute + fp16 convert ----------------
// blockIdx.z encodes (which, e); thread handles k-pairs -> half2 staging stores
__global__ void w_perm_kernel(const float* __restrict__ W1,
                              const float* __restrict__ W2) {
    __shared__ __half stg[4096];
    const int which = blockIdx.z >> 3;
    const int e     = blockIdx.z & 7;
    const float* W  = which ? W2 : W1;
    __half* dst     = which ? g_W2h : g_W1h;
    const int kt = blockIdx.x, nb = blockIdx.y;
    const int tid = threadIdx.x;
    const int kp  = tid >> 4;          // k-pair 0..15 (k = 2*kp, 2*kp+1)
    const int nc  = tid & 15;          // column group (8 n each)
    const float* Ws = W + (size_t)e * D_MODEL * D_MODEL;
    __half2* stg2 = (__half2*)stg;
#pragma unroll
    for (int i = 0; i < 2; i++) {
        int n_in = nc * 8 + i * 4;
        const float* r0 = Ws + (size_t)(kt * 32 + 2 * kp) * D_MODEL + nb * 128 + n_in;
        float4 v0 = *(const float4*)r0;
        float4 v1 = *(const float4*)(r0 + D_MODEL);
        stg2[b_fidx16(n_in + 0, 2 * kp) >> 1] = __floats2half2_rn(v0.x, v1.x);
        stg2[b_fidx16(n_in + 1, 2 * kp) >> 1] = __floats2half2_rn(v0.y, v1.y);
        stg2[b_fidx16(n_in + 2, 2 * kp) >> 1] = __floats2half2_rn(v0.z, v1.z);
        stg2[b_fidx16(n_in + 3, 2 * kp) >> 1] = __floats2half2_rn(v0.w, v1.w);
    }
    __syncthreads();
    uint4* d4 = (uint4*)(dst + ((size_t)(e * 8 + nb) * KTILES + kt) * 4096);
    const uint4* s4 = (const uint4*)stg;
    d4[tid]       = s4[tid];
    d4[tid + 256] = s4[tid + 256];
}

// ---------------- kernel: gather + fp16 convert + permute X -> g_A1h ------
// One block per (mb, e, kt): load 128x32 sub-tile, stage, single barrier, copy.
__global__ void a1_perm_kernel(const float* __restrict__ x) {
    __shared__ __half stg[4096];
    const int mb = blockIdx.x, e = blockIdx.y, kt = blockIdx.z;
    const int cnt = g_cnt[e];
    if (mb * BM >= cnt) return;
    const int tid  = threadIdx.x;
    const int r    = tid >> 1;         // row 0..127
    const int hlf  = tid & 1;          // k-half (16 each)
    int ai  = mb * BM + r;
    int tok = (ai < cnt) ? g_tok[e * CAP + ai] : g_tok[e * CAP];
    const float* src = x + (size_t)tok * D_MODEL + kt * 32 + hlf * 16;

#pragma unroll
    for (int i = 0; i < 4; i++) {
        int k_in = hlf * 16 + i * 4;
        float4 v = *(const float4*)(src + i * 4);
        stg[a_fidx16(r, k_in + 0)] = __float2half_rn(v.x);
        stg[a_fidx16(r, k_in + 1)] = __float2half_rn(v.y);
        stg[a_fidx16(r, k_in + 2)] = __float2half_rn(v.z);
        stg[a_fidx16(r, k_in + 3)] = __float2half_rn(v.w);
    }
    __syncthreads();
    uint4* d4 = (uint4*)(g_A1h + ((size_t)(e * MB_MAX + mb) * KTILES + kt) * 4096);
    const uint4* s4 = (const uint4*)stg;
    d4[tid]       = s4[tid];
    d4[tid + 256] = s4[tid + 256];
}

// ---------------- kernel: grouped GEMM (fp16, 4-stage deep pipeline) -------
// BM=128, BN=128, 128 threads, 4 warps (2m x 2n), warp tile 64x64.
// 4-stage cp.async ring (16KB/stage), wait_group 2, one barrier per k-tile,
// 2 CTAs/SM.
template <bool FIRST>
__global__ void __launch_bounds__(NTHREADS, 2)
moe_gemm(const float* __restrict__ bias, float* __restrict__ out) {
    const int e   = blockIdx.z;
    const int cnt = g_cnt[e];
    const int mb  = blockIdx.y;
    if (mb * BM >= cnt) return;
    const int nb  = blockIdx.x;

    extern __shared__ __align__(128) char smem[];
    const uint32_t sb = smem_u32(smem);
    const int tid  = threadIdx.x;
    const int lane = tid & 31;
    const int warp = tid >> 5;
    const int wm   = warp >> 1;          // 0..1 (64-row)
    const int wn   = warp & 1;           // 0..1 (64-col)
    const int g    = lane >> 2;
    const int tg   = lane & 3;

    const __half* Asrc = (FIRST ? g_A1h : g_A2h) + (size_t)(e * MB_MAX + mb) * KTILES * 4096;
    const __half* Bsrc = (FIRST ? g_W1h : g_W2h) + (size_t)(e * 8 + nb) * KTILES * 4096;

    float c[32][4];
#pragma unroll
    for (int i = 0; i < 32; i++)
#pragma unroll
        for (int j = 0; j < 4; j++) c[i][j] = 0.f;

    // stage layout: [0,8K) A | [8K,16K) B
    auto load_stage = [&](int kt, int s) {
        uint32_t da = sb + s * STAGE_B + tid * 16;
        const char* sa = (const char*)(Asrc + (size_t)kt * 4096) + tid * 16;
        const char* sw = (const char*)(Bsrc + (size_t)kt * 4096) + tid * 16;
#pragma unroll
        for (int cc = 0; cc < 4; cc++) {
            CP_ASYNC16(da + cc * 2048,        sa + cc * 2048);
            CP_ASYNC16(da + 8192 + cc * 2048, sw + cc * 2048);
        }
    };

    load_stage(0, 0); CP_COMMIT();
    load_stage(1, 1); CP_COMMIT();
    load_stage(2, 2); CP_COMMIT();

    const uint32_t aoff = wm * 4096 + lane * 16;          // A frag base (bytes)
    const uint32_t boff = 8192 + wn * 4096 + lane * 8;    // B frag base (bytes)

    for (int it = 0; it < KTILES; it++) {
        CP_WAIT2();
        __syncthreads();
        // stage (it+3)&3 == (it-1)&3: its reads finished at prev barrier
        if (it + 3 < KTILES) load_stage(it + 3, (it + 3) & 3);
        CP_COMMIT();

        const uint32_t st = sb + (it & 3) * STAGE_B;
#pragma unroll
        for (int kk = 0; kk < 2; kk++) {
            uint32_t a[4][4], b[8][2];
#pragma unroll
            for (int mi = 0; mi < 4; mi++)
                LDS128(a[mi], st + aoff + mi * 1024 + kk * 512);
#pragma unroll
            for (int ni = 0; ni < 8; ni++)
                LDS64(b[ni], st + boff + ni * 512 + kk * 256);
#pragma unroll
            for (int mi = 0; mi < 4; mi++)
#pragma unroll
                for (int ni = 0; ni < 8; ni++)
                    mma_f16(c[mi * 8 + ni], a[mi], b[ni]);
        }
    }

    // ---- epilogue ----
    const float* brow = bias + e * D_MODEL;
#pragma unroll
    for (int mi = 0; mi < 4; mi++) {
#pragma unroll
        for (int ni = 0; ni < 8; ni++) {
#pragma unroll
            for (int j = 0; j < 4; j++) {
                int r_blk = wm * 64 + mi * 16 + g + 8 * (j >> 1);
                int grow  = mb * BM + r_blk;
                if (grow >= cnt) continue;
                int n_glob = nb * BN + wn * 64 + ni * 8 + 2 * tg + (j & 1);
                float v = c[mi * 8 + ni][j] + __ldg(brow + n_glob);
                if (FIRST) {
                    v = fmaxf(v, 0.f);
                    int kt = n_glob >> 5, k_in = n_glob & 31;
                    g_A2h[((size_t)(e * MB_MAX + mb) * KTILES + kt) * 4096 +
                          a_fidx16(r_blk, k_in)] = __float2half_rn(v);
                } else {
                    float w = g_wgt[e * CAP + grow];
                    atomicAdd(out + (size_t)g_tok[e * CAP + grow] * D_MODEL + n_glob,
                              v * w);
                }
            }
        }
    }
}

// ---------------- launch ----------------
extern "C" void kernel_launch(void* const* d_in, const int* in_sizes, int n_in,
                              void* d_out, int out_size) {
    const float* x  = (const float*)d_in[0];
    const float* Wg = (const float*)d_in[1];
    const float* bg = (const float*)d_in[2];
    const float* W1 = (const float*)d_in[3];
    const float* b1 = (const float*)d_in[4];
    const float* W2 = (const float*)d_in[5];
    const float* b2 = (const float*)d_in[6];
    float* out = (float*)d_out;

    cudaFuncSetAttribute(moe_gemm<true>,
                         cudaFuncAttributeMaxDynamicSharedMemorySize, SMEM_T);
    cudaFuncSetAttribute(moe_gemm<false>,
                         cudaFuncAttributeMaxDynamicSharedMemorySize, SMEM_T);

    cudaMemsetAsync(out, 0, (size_t)out_size * sizeof(float));
    zero_cnt_kernel<<<1, 32>>>();
    gate_kernel<<<N_TOK / 8, 256>>>(x, Wg, bg);

    dim3 wg(KTILES, 8, 16);                 // fused W1+W2 permute
    w_perm_kernel<<<wg, 256>>>(W1, W2);
    a1_perm_kernel<<<dim3(MB_MAX, N_EXP, KTILES), 256>>>(x);

    dim3 grid(D_MODEL / BN, MB_MAX, N_EXP);   // (8, 64, 8)
    moe_gemm<true><<<grid, NTHREADS, SMEM_T>>>(b1, nullptr);
    moe_gemm<false><<<grid, NTHREADS, SMEM_T>>>(b2, out);
}

// round 16
// speedup vs baseline: 1.3355x; 1.0580x over previous
#include <cuda_runtime.h>
#include <cuda_fp16.h>
#include <cstdint>

#define D_MODEL 1024
#define N_EXP   8
#define N_TOK   8192
#define CAP     8192
#define MB_MAX  64
#define BM      128
#define BN      128
#define KTILES  32
#define NTHREADS 128
#define STAGE_B 16384         // 8KB A + 8KB B per stage
#define NSTAGE  4
#define SMEM_T  (NSTAGE * STAGE_B) // 64 KB

// ---------------- device scratch ----------------
__device__ int    g_cnt[N_EXP];
__device__ int    g_tok[N_EXP * CAP];
__device__ float  g_wgt[N_EXP * CAP];
// fragment-permuted fp16 tiles: [e][mb][kt][4096 halves]
__device__ __half g_A1h[(size_t)N_EXP * MB_MAX * KTILES * 4096];
__device__ __half g_A2h[(size_t)N_EXP * MB_MAX * KTILES * 4096];
// fragment-permuted fp16 weights: [e][nb(8)][kt][4096 halves]
__device__ __half g_W1h[(size_t)N_EXP * 8 * KTILES * 4096];
__device__ __half g_W2h[(size_t)N_EXP * 8 * KTILES * 4096];

// ---------------- helpers ----------------
__device__ __forceinline__ uint32_t smem_u32(const void* p) {
    uint32_t a;
    asm("{ .reg .u64 t; cvta.to.shared.u64 t, %1; cvt.u32.u64 %0, t; }" : "=r"(a) : "l"(p));
    return a;
}
__device__ __forceinline__ void mma_f16(float* c, const uint32_t* a, const uint32_t* b) {
    asm volatile(
        "mma.sync.aligned.m16n8k16.row.col.f32.f16.f16.f32 "
        "{%0,%1,%2,%3}, {%4,%5,%6,%7}, {%8,%9}, {%0,%1,%2,%3};"
        : "+f"(c[0]), "+f"(c[1]), "+f"(c[2]), "+f"(c[3])
        : "r"(a[0]), "r"(a[1]), "r"(a[2]), "r"(a[3]),
          "r"(b[0]), "r"(b[1]));
}
#define CP_ASYNC16(dst, src) \
    asm volatile("cp.async.cg.shared.global [%0], [%1], 16;" :: "r"(dst), "l"(src))
#define CP_COMMIT()  asm volatile("cp.async.commit_group;" ::: "memory")
#define CP_WAIT2()   asm volatile("cp.async.wait_group 2;" ::: "memory")
#define CP_WAIT0()   asm volatile("cp.async.wait_group 0;" ::: "memory")
#define LDS128(r, a) \
    asm volatile("ld.shared.v4.b32 {%0,%1,%2,%3}, [%4];" \
        : "=r"((r)[0]), "=r"((r)[1]), "=r"((r)[2]), "=r"((r)[3]) : "r"(a))
#define LDS64(r, a) \
    asm volatile("ld.shared.v2.b32 {%0,%1}, [%2];" \
        : "=r"((r)[0]), "=r"((r)[1]) : "r"(a))

// fp16 m16n8k16 fragment slots (indices in halves), r in 0..127, k in 0..31
__device__ __forceinline__ int a_fidx16(int r, int k) {
    return (((r >> 4) * 2 + (k >> 4)) << 8) +
           (((r & 7) * 4 + ((k >> 1) & 3)) << 3) +
           ((((r >> 3) & 1) + 2 * ((k >> 3) & 1)) << 1) + (k & 1);
}
__device__ __forceinline__ int b_fidx16(int n, int k) {
    return (((n >> 3) * 2 + (k >> 4)) << 7) +
           (((n & 7) * 4 + ((k >> 1) & 3)) << 2) +
           (((k >> 3) & 1) << 1) + (k & 1);
}

// ---------------- kernel: reset counters ----------------
__global__ void zero_cnt_kernel() {
    if (threadIdx.x < N_EXP) g_cnt[threadIdx.x] = 0;
}

// ---------------- kernel: gating + top-2 ----------------
__global__ void gate_kernel(const float* __restrict__ x,
                            const float* __restrict__ Wg,
                            const float* __restrict__ bg) {
    int tok  = blockIdx.x * 8 + (threadIdx.x >> 5);
    int lane = threadIdx.x & 31;
    if (tok >= N_TOK) return;
    const float* xr = x + (size_t)tok * D_MODEL;

    float s[8];
#pragma unroll
    for (int e = 0; e < 8; e++) s[e] = 0.f;
    for (int k = lane; k < D_MODEL; k += 32) {
        float xv = xr[k];
        const float4* wr = (const float4*)(Wg + (size_t)k * N_EXP);
        float4 w0 = wr[0], w1 = wr[1];
        s[0] += xv * w0.x; s[1] += xv * w0.y; s[2] += xv * w0.z; s[3] += xv * w0.w;
        s[4] += xv * w1.x; s[5] += xv * w1.y; s[6] += xv * w1.z; s[7] += xv * w1.w;
    }
#pragma unroll
    for (int e = 0; e < 8; e++)
#pragma unroll
        for (int off = 16; off > 0; off >>= 1)
            s[e] += __shfl_xor_sync(0xffffffffu, s[e], off);

    if (lane == 0) {
        float best = -3.4e38f, best2 = -3.4e38f;
        int e0 = 0, e1 = 0;
#pragma unroll
        for (int e = 0; e < 8; e++) {
            float v = s[e] + bg[e];
            if (v > best)       { best2 = best; e1 = e0; best = v; e0 = e; }
            else if (v > best2) { best2 = v; e1 = e; }
        }
        int p0 = atomicAdd(&g_cnt[e0], 1);
        g_tok[e0 * CAP + p0] = tok;
        g_wgt[e0 * CAP + p0] = best;
        int p1 = atomicAdd(&g_cnt[e1], 1);
        g_tok[e1 * CAP + p1] = tok;
        g_wgt[e1 * CAP + p1] = best2;
    }
}

// ---------------- kernel: fused weight permute + fp16 convert ----------------
__global__ void w_perm_kernel(const float* __restrict__ W1,
                              const float* __restrict__ W2) {
    __shared__ __half stg[4096];
    const int which = blockIdx.z >> 3;
    const int e     = blockIdx.z & 7;
    const float* W  = which ? W2 : W1;
    __half* dst     = which ? g_W2h : g_W1h;
    const int kt = blockIdx.x, nb = blockIdx.y;
    const int tid = threadIdx.x;
    const int kp  = tid >> 4;          // k-pair 0..15
    const int nc  = tid & 15;          // column group (8 n each)
    const float* Ws = W + (size_t)e * D_MODEL * D_MODEL;
    __half2* stg2 = (__half2*)stg;
#pragma unroll
    for (int i = 0; i < 2; i++) {
        int n_in = nc * 8 + i * 4;
        const float* r0 = Ws + (size_t)(kt * 32 + 2 * kp) * D_MODEL + nb * 128 + n_in;
        float4 v0 = *(const float4*)r0;
        float4 v1 = *(const float4*)(r0 + D_MODEL);
        stg2[b_fidx16(n_in + 0, 2 * kp) >> 1] = __floats2half2_rn(v0.x, v1.x);
        stg2[b_fidx16(n_in + 1, 2 * kp) >> 1] = __floats2half2_rn(v0.y, v1.y);
        stg2[b_fidx16(n_in + 2, 2 * kp) >> 1] = __floats2half2_rn(v0.z, v1.z);
        stg2[b_fidx16(n_in + 3, 2 * kp) >> 1] = __floats2half2_rn(v0.w, v1.w);
    }
    __syncthreads();
    uint4* d4 = (uint4*)(dst + ((size_t)(e * 8 + nb) * KTILES + kt) * 4096);
    const uint4* s4 = (const uint4*)stg;
    d4[tid]       = s4[tid];
    d4[tid + 256] = s4[tid + 256];
}

// ---------------- kernel: gather + fp16 convert + permute X -> g_A1h ------
__global__ void a1_perm_kernel(const float* __restrict__ x) {
    __shared__ __half stg[4096];
    const int mb = blockIdx.x, e = blockIdx.y, kt = blockIdx.z;
    const int cnt = g_cnt[e];
    if (mb * BM >= cnt) return;
    const int tid  = threadIdx.x;
    const int r    = tid >> 1;
    const int hlf  = tid & 1;
    int ai  = mb * BM + r;
    int tok = (ai < cnt) ? g_tok[e * CAP + ai] : g_tok[e * CAP];
    const float* src = x + (size_t)tok * D_MODEL + kt * 32 + hlf * 16;

#pragma unroll
    for (int i = 0; i < 4; i++) {
        int k_in = hlf * 16 + i * 4;
        float4 v = *(const float4*)(src + i * 4);
        stg[a_fidx16(r, k_in + 0)] = __float2half_rn(v.x);
        stg[a_fidx16(r, k_in + 1)] = __float2half_rn(v.y);
        stg[a_fidx16(r, k_in + 2)] = __float2half_rn(v.z);
        stg[a_fidx16(r, k_in + 3)] = __float2half_rn(v.w);
    }
    __syncthreads();
    uint4* d4 = (uint4*)(g_A1h + ((size_t)(e * MB_MAX + mb) * KTILES + kt) * 4096);
    const uint4* s4 = (const uint4*)stg;
    d4[tid]       = s4[tid];
    d4[tid + 256] = s4[tid + 256];
}

// ---------------- kernel: grouped GEMM (fp16, 4-stage deep pipeline) -------
// BM=128, BN=128, 128 threads, 4 warps (2m x 2n), warp tile 64x64.
// GEMM1 epilogue staged through smem -> contiguous 32KB coalesced store.
template <bool FIRST>
__global__ void __launch_bounds__(NTHREADS, 2)
moe_gemm(const float* __restrict__ bias, float* __restrict__ out) {
    const int e   = blockIdx.z;
    const int cnt = g_cnt[e];
    const int mb  = blockIdx.y;
    if (mb * BM >= cnt) return;
    const int nb  = blockIdx.x;

    extern __shared__ __align__(128) char smem[];
    const uint32_t sb = smem_u32(smem);
    const int tid  = threadIdx.x;
    const int lane = tid & 31;
    const int warp = tid >> 5;
    const int wm   = warp >> 1;          // 0..1 (64-row)
    const int wn   = warp & 1;           // 0..1 (64-col)
    const int g    = lane >> 2;
    const int tg   = lane & 3;

    const __half* Asrc = (FIRST ? g_A1h : g_A2h) + (size_t)(e * MB_MAX + mb) * KTILES * 4096;
    const __half* Bsrc = (FIRST ? g_W1h : g_W2h) + (size_t)(e * 8 + nb) * KTILES * 4096;

    float c[32][4];
#pragma unroll
    for (int i = 0; i < 32; i++)
#pragma unroll
        for (int j = 0; j < 4; j++) c[i][j] = 0.f;

    // stage layout: [0,8K) A | [8K,16K) B
    auto load_stage = [&](int kt, int s) {
        uint32_t da = sb + s * STAGE_B + tid * 16;
        const char* sa = (const char*)(Asrc + (size_t)kt * 4096) + tid * 16;
        const char* sw = (const char*)(Bsrc + (size_t)kt * 4096) + tid * 16;
#pragma unroll
        for (int cc = 0; cc < 4; cc++) {
            CP_ASYNC16(da + cc * 2048,        sa + cc * 2048);
            CP_ASYNC16(da + 8192 + cc * 2048, sw + cc * 2048);
        }
    };

    load_stage(0, 0); CP_COMMIT();
    load_stage(1, 1); CP_COMMIT();
    load_stage(2, 2); CP_COMMIT();

    const uint32_t aoff = wm * 4096 + lane * 16;          // A frag base (bytes)
    const uint32_t boff = 8192 + wn * 4096 + lane * 8;    // B frag base (bytes)

    for (int it = 0; it < KTILES; it++) {
        CP_WAIT2();
        __syncthreads();
        if (it + 3 < KTILES) load_stage(it + 3, (it + 3) & 3);
        CP_COMMIT();

        const uint32_t st = sb + (it & 3) * STAGE_B;
#pragma unroll
        for (int kk = 0; kk < 2; kk++) {
            uint32_t a[4][4], b[8][2];
#pragma unroll
            for (int mi = 0; mi < 4; mi++)
                LDS128(a[mi], st + aoff + mi * 1024 + kk * 512);
#pragma unroll
            for (int ni = 0; ni < 8; ni++)
                LDS64(b[ni], st + boff + ni * 512 + kk * 256);
#pragma unroll
            for (int mi = 0; mi < 4; mi++)
#pragma unroll
                for (int ni = 0; ni < 8; ni++)
                    mma_f16(c[mi * 8 + ni], a[mi], b[ni]);
        }
    }

    // ---- epilogue ----
    const float* brow = bias + e * D_MODEL;
    if (FIRST) {
        // stage permuted relu(bias+acc) tile in smem, then coalesced copy-out
        CP_WAIT0();
        __syncthreads();
        __half2* ep2 = (__half2*)smem;
#pragma unroll
        for (int mi = 0; mi < 4; mi++) {
#pragma unroll
            for (int ni = 0; ni < 8; ni++) {
#pragma unroll
                for (int jp = 0; jp < 2; jp++) {
                    int r_blk = wm * 64 + mi * 16 + g + 8 * jp;
                    int n0    = wn * 64 + ni * 8 + 2 * tg;     // even, 0..126
                    int n_glob = nb * BN + n0;
                    float v0 = fmaxf(c[mi * 8 + ni][jp * 2 + 0] + __ldg(brow + n_glob), 0.f);
                    float v1 = fmaxf(c[mi * 8 + ni][jp * 2 + 1] + __ldg(brow + n_glob + 1), 0.f);
                    int idx = (n0 >> 5) * 4096 + a_fidx16(r_blk, n0 & 31);  // even
                    ep2[idx >> 1] = __floats2half2_rn(v0, v1);
                }
            }
        }
        __syncthreads();
        uint4* d4 = (uint4*)(g_A2h + ((size_t)(e * MB_MAX + mb) * KTILES + nb * 4) * 4096);
        const uint4* s4 = (const uint4*)smem;
#pragma unroll
        for (int i = 0; i < 16; i++)
            d4[tid + i * 128] = s4[tid + i * 128];
    } else {
#pragma unroll
        for (int mi = 0; mi < 4; mi++) {
#pragma unroll
            for (int ni = 0; ni < 8; ni++) {
#pragma unroll
                for (int j = 0; j < 4; j++) {
                    int r_blk = wm * 64 + mi * 16 + g + 8 * (j >> 1);
                    int grow  = mb * BM + r_blk;
                    if (grow >= cnt) continue;
                    int n_glob = nb * BN + wn * 64 + ni * 8 + 2 * tg + (j & 1);
                    float v = c[mi * 8 + ni][j] + __ldg(brow + n_glob);
                    float w = g_wgt[e * CAP + grow];
                    atomicAdd(out + (size_t)g_tok[e * CAP + grow] * D_MODEL + n_glob,
                              v * w);
                }
            }
        }
    }
}

// ---------------- launch ----------------
extern "C" void kernel_launch(void* const* d_in, const int* in_sizes, int n_in,
                              void* d_out, int out_size) {
    const float* x  = (const float*)d_in[0];
    const float* Wg = (const float*)d_in[1];
    const float* bg = (const float*)d_in[2];
    const float* W1 = (const float*)d_in[3];
    const float* b1 = (const float*)d_in[4];
    const float* W2 = (const float*)d_in[5];
    const float* b2 = (const float*)d_in[6];
    float* out = (float*)d_out;

    cudaFuncSetAttribute(moe_gemm<true>,
                         cudaFuncAttributeMaxDynamicSharedMemorySize, SMEM_T);
    cudaFuncSetAttribute(moe_gemm<false>,
                         cudaFuncAttributeMaxDynamicSharedMemorySize, SMEM_T);

    cudaMemsetAsync(out, 0, (size_t)out_size * sizeof(float));
    zero_cnt_kernel<<<1, 32>>>();
    gate_kernel<<<N_TOK / 8, 256>>>(x, Wg, bg);

    dim3 wg(KTILES, 8, 16);                 // fused W1+W2 permute
    w_perm_kernel<<<wg, 256>>>(W1, W2);
    a1_perm_kernel<<<dim3(MB_MAX, N_EXP, KTILES), 256>>>(x);

    dim3 grid(D_MODEL / BN, MB_MAX, N_EXP);   // (8, 64, 8)
    moe_gemm<true><<<grid, NTHREADS, SMEM_T>>>(b1, nullptr);
    moe_gemm<false><<<grid, NTHREADS, SMEM_T>>>(b2, out);
}